// round 2
// baseline (speedup 1.0000x reference)
#include <cuda_runtime.h>
#include <cuda_bf16.h>

typedef unsigned long long ull;

#define BATCH 64
#define SEQ   512
#define NIN   50
#define NK    4
#define IK    200
#define HFC   1024
#define NOUT  128
#define HR    512
#define BS    (BATCH*SEQ)   // 32768

// ---------------- scratch (static device memory; no allocs) ----------------
__device__ float g_Z[BS * IK];          // fuzzy output [32768,200]
__device__ float g_H1[NOUT * HFC];      // fc3@fc2   [128,1024]
__device__ float g_H2[NOUT * HFC];      // H1@fc1    [128,1024]
__device__ float g_H3[NOUT * IK];       // H2@fc0    [128,200]
__device__ float g_W2[HR * IK];         // w_ih0@H3  [512,200]
__device__ float g_c1[HFC];
__device__ float g_c2[HFC];
__device__ float g_c3[NOUT];
__device__ float g_b2[HR];
__device__ float g_bp1[HR];
__device__ float g_pre0[(size_t)BS * HR];   // 64MB
__device__ float g_h0[(size_t)BS * HR];     // 64MB
__device__ float g_pre1[(size_t)BS * HR];   // 64MB

// ---------------- packed f32x2 helpers ----------------
__device__ __forceinline__ void ffma2(ull& c, ull a, ull b) {
    asm("fma.rn.f32x2 %0, %1, %2, %0;" : "+l"(c) : "l"(a), "l"(b));
}
__device__ __forceinline__ ull pack2(float x, float y) {
    ull r; asm("mov.b64 %0, {%1, %2};" : "=l"(r) : "f"(x), "f"(y)); return r;
}
__device__ __forceinline__ float2 unpack2(ull v) {
    float2 r; asm("mov.b64 {%0, %1}, %2;" : "=f"(r.x), "=f"(r.y) : "l"(v)); return r;
}
__device__ __forceinline__ unsigned smem_u32(const void* p) {
    unsigned a;
    asm("{ .reg .u64 t; cvta.to.shared.u64 t, %1; cvt.u32.u64 %0, t; }" : "=r"(a) : "l"(p));
    return a;
}

// ---------------- fuzzy layer ----------------
__global__ void fuzzy_kernel(const float* __restrict__ x,
                             const float* __restrict__ fp,
                             float* __restrict__ Z) {
    int idx = blockIdx.x * blockDim.x + threadIdx.x;
    if (idx >= BS * IK) return;
    int bs = idx / IK;
    int c  = idx - bs * IK;       // c = k*50 + i
    int i  = c % NIN;
    float xv  = x[bs * NIN + i];
    float mu  = fp[2 * c];
    float sig = fp[2 * c + 1];
    float d = xv - mu;
    Z[idx] = expf(-(d * d) / sig);
}

// ---------------- generic fp32 GEMM ----------------
// C[M,N] = A[M,K] @ op(B) + bias,  BT: B is [N,K] (use B^T), else B is [K,N].
// Requires (BM/TM)*(BN/TN) == NT threads; BM==BN when BT.
template<int BM, int BN, int BK, int TM, int TN, bool BT, int NT>
__global__ void __launch_bounds__(NT, 2)
gemm_f32(const float* __restrict__ A, const float* __restrict__ B,
         const float* __restrict__ bias, float* __restrict__ C,
         int M, int N, int Kd) {
    __shared__ __align__(16) float As[BK][BM];
    __shared__ __align__(16) float Bs[BK][BN];
    const int tid = threadIdx.x;
    const int TX  = BN / TN;
    const int tx  = tid % TX;
    const int ty  = tid / TX;
    const int m0  = blockIdx.y * BM;
    const int n0  = blockIdx.x * BN;

    ull acc[TM][TN / 2];
#pragma unroll
    for (int i = 0; i < TM; i++)
#pragma unroll
        for (int j = 0; j < TN / 2; j++) acc[i][j] = 0ull;

    const int AKV = BK / 4;                 // float4s per row in K
    const int a_r = tid / AKV;
    const int a_k = (tid % AKV) * 4;
    const int AROWS = NT / AKV;

    const int kTiles = (Kd + BK - 1) / BK;
    for (int kt = 0; kt < kTiles; kt++) {
        const int k0 = kt * BK;
        // --- load A tile (transpose to k-major) ---
#pragma unroll
        for (int r = a_r; r < BM; r += AROWS) {
            float4 v = make_float4(0.f, 0.f, 0.f, 0.f);
            int gm = m0 + r, gk = k0 + a_k;
            if (gm < M && gk < Kd)
                v = *(const float4*)(A + (size_t)gm * Kd + gk);
            As[a_k + 0][r] = v.x; As[a_k + 1][r] = v.y;
            As[a_k + 2][r] = v.z; As[a_k + 3][r] = v.w;
        }
        // --- load B tile ---
        if (BT) {
#pragma unroll
            for (int r = a_r; r < BN; r += AROWS) {
                float4 v = make_float4(0.f, 0.f, 0.f, 0.f);
                int gn = n0 + r, gk = k0 + a_k;
                if (gn < N && gk < Kd)
                    v = *(const float4*)(B + (size_t)gn * Kd + gk);
                Bs[a_k + 0][r] = v.x; Bs[a_k + 1][r] = v.y;
                Bs[a_k + 2][r] = v.z; Bs[a_k + 3][r] = v.w;
            }
        } else {
            const int BNV = BN / 4;
            const int b_c = (tid % BNV) * 4;
            const int b_r0 = tid / BNV;
            const int BSTEP = NT / BNV;
#pragma unroll
            for (int r = b_r0; r < BK; r += BSTEP) {
                float4 v = make_float4(0.f, 0.f, 0.f, 0.f);
                int gk = k0 + r, gn = n0 + b_c;
                if (gk < Kd && gn < N)
                    v = *(const float4*)(B + (size_t)gk * N + gn);
                *(float4*)&Bs[r][b_c] = v;
            }
        }
        __syncthreads();
        // --- compute ---
#pragma unroll
        for (int k = 0; k < BK; k++) {
            float a[TM];
#pragma unroll
            for (int i = 0; i < TM; i += 4)
                *(float4*)&a[i] = *(const float4*)&As[k][ty * TM + i];
            ull bp[TN / 2];
#pragma unroll
            for (int j = 0; j < TN; j += 4) {
                ulonglong2 b2v = *(const ulonglong2*)&Bs[k][tx * TN + j];
                bp[j / 2]     = b2v.x;
                bp[j / 2 + 1] = b2v.y;
            }
#pragma unroll
            for (int i = 0; i < TM; i++) {
                ull ad = pack2(a[i], a[i]);
#pragma unroll
                for (int jp = 0; jp < TN / 2; jp++) ffma2(acc[i][jp], ad, bp[jp]);
            }
        }
        __syncthreads();
    }
    // --- epilogue ---
#pragma unroll
    for (int i = 0; i < TM; i++) {
        int gm = m0 + ty * TM + i;
        if (gm >= M) continue;
#pragma unroll
        for (int jp = 0; jp < TN / 2; jp++) {
            float2 c2 = unpack2(acc[i][jp]);
            int gn = n0 + tx * TN + jp * 2;
            if (gn < N)     C[(size_t)gm * N + gn]     = c2.x + (bias ? bias[gn]     : 0.f);
            if (gn + 1 < N) C[(size_t)gm * N + gn + 1] = c2.y + (bias ? bias[gn + 1] : 0.f);
        }
    }
}

// ---------------- small vec = W@v + b1 + b2 ----------------
__global__ void vecmat(const float* __restrict__ W, const float* __restrict__ v,
                       const float* __restrict__ b1, const float* __restrict__ b2,
                       float* __restrict__ out, int M, int Kd) {
    int m = blockIdx.x * blockDim.x + threadIdx.x;
    if (m >= M) return;
    float s = 0.f;
    const float* wr = W + (size_t)m * Kd;
    for (int k = 0; k < Kd; k++) s += wr[k] * v[k];
    if (b1) s += b1[m];
    if (b2) s += b2[m];
    out[m] = s;
}

__global__ void add2(const float* __restrict__ a, const float* __restrict__ b,
                     float* __restrict__ o, int n) {
    int i = blockIdx.x * blockDim.x + threadIdx.x;
    if (i < n) o[i] = a[i] + b[i];
}

// ---------------- RNN recurrence: persistent cluster kernel ----------------
// 16 clusters x 8 CTAs; cluster c handles batches [4c,4c+4); CTA rank holds
// W_hh rows [64*rank, 64*rank+64) in registers (packed f32x2).
// h_new[b][j] = tanh(pre[b][s][j] + sum_k h[b][k] * W[j][k])
__global__ void __cluster_dims__(8, 1, 1) __launch_bounds__(256, 1)
rnn_kernel(const float* __restrict__ pre, const float* __restrict__ Whh,
           float* __restrict__ hout) {
    __shared__ __align__(16) float hbuf[2][4][HR];   // 16 KB, double buffered
    __shared__ float red[4][4][64];                  // [batch][kchunk][j]

    const int t = threadIdx.x;
    unsigned rank;
    asm("mov.u32 %0, %%cluster_ctarank;" : "=r"(rank));
    const int cid = blockIdx.x >> 3;
    const int j   = t & 63;
    const int kc  = t >> 6;                // also final-stage batch index
    const int row = (int)rank * 64 + j;

    // load W slice: thread owns row `row`, k in [kc*128, kc*128+128), packed pairs
    ull wpk[64];
    {
        const ulonglong2* wq =
            (const ulonglong2*)(Whh + (size_t)row * HR + kc * 128);
#pragma unroll
        for (int i = 0; i < 32; i++) {
            ulonglong2 v = wq[i];
            wpk[2 * i]     = v.x;
            wpk[2 * i + 1] = v.y;
        }
    }

    // zero h buffer 0 (h_0 = 0)
    for (int i = t; i < 4 * HR; i += 256) ((float*)hbuf[0])[i] = 0.f;
    __syncthreads();

    const int b0 = cid * 4;
    // thread's final-stage element: batch b0+kc, column rank*64+j
    const size_t gidx0 = ((size_t)(b0 + kc) * SEQ) * HR + (size_t)rank * 64 + j;
    const float* preP = pre + gidx0;
    float* houtP = hout + gidx0;

    const unsigned hb_base = smem_u32(&hbuf[0][0][0]);
    const unsigned dst_off = ((unsigned)kc * HR + rank * 64 + j) * 4u;

    int cur = 0;
    for (int s = 0; s < SEQ; s++) {
        const float pv = preP[(size_t)s * HR];   // prefetch, overlaps compute
        // partial dot products: (j, kc) x 4 batches
#pragma unroll
        for (int b = 0; b < 4; b++) {
            const ulonglong2* hp =
                (const ulonglong2*)&hbuf[cur][b][kc * 128];
            ull acc0 = 0ull, acc1 = 0ull;
#pragma unroll
            for (int i = 0; i < 32; i++) {
                ulonglong2 h2 = hp[i];
                ffma2(acc0, wpk[2 * i], h2.x);
                ffma2(acc1, wpk[2 * i + 1], h2.y);
            }
            float2 s0 = unpack2(acc0), s1 = unpack2(acc1);
            red[b][kc][j] = (s0.x + s0.y) + (s1.x + s1.y);
        }
        __syncthreads();
        // finalize: batch = kc, col = rank*64+j
        float v = red[kc][0][j] + red[kc][1][j] + red[kc][2][j] + red[kc][3][j] + pv;
        float hn = tanhf(v);
        houtP[(size_t)s * HR] = hn;
        // broadcast to all 8 CTAs' next buffer
        const int nxt = cur ^ 1;
        unsigned dst = hb_base + (unsigned)nxt * (4 * HR * 4) + dst_off;
#pragma unroll
        for (int p = 0; p < 8; p++) {
            unsigned rp;
            asm("mapa.shared::cluster.u32 %0, %1, %2;" : "=r"(rp) : "r"(dst), "r"(p));
            asm volatile("st.shared::cluster.f32 [%0], %1;" :: "r"(rp), "f"(hn));
        }
        asm volatile("barrier.cluster.arrive.aligned;" ::: "memory");
        asm volatile("barrier.cluster.wait.aligned;" ::: "memory");
        cur = nxt;
    }
}

// ---------------- host ----------------
extern "C" void kernel_launch(void* const* d_in, const int* in_sizes, int n_in,
                              void* d_out, int out_size) {
    const float* x     = (const float*)d_in[0];
    const float* fp    = (const float*)d_in[1];
    const float* fc0w  = (const float*)d_in[2];
    const float* fc0b  = (const float*)d_in[3];
    const float* fc1w  = (const float*)d_in[4];
    const float* fc1b  = (const float*)d_in[5];
    const float* fc2w  = (const float*)d_in[6];
    const float* fc2b  = (const float*)d_in[7];
    const float* fc3w  = (const float*)d_in[8];
    const float* fc3b  = (const float*)d_in[9];
    const float* wih0  = (const float*)d_in[10];
    const float* whh0  = (const float*)d_in[11];
    const float* bih0  = (const float*)d_in[12];
    const float* bhh0  = (const float*)d_in[13];
    const float* wih1  = (const float*)d_in[14];
    const float* whh1  = (const float*)d_in[15];
    const float* bih1  = (const float*)d_in[16];
    const float* bhh1  = (const float*)d_in[17];
    float* out = (float*)d_out;

    float *Z, *H1, *H2, *H3, *W2, *c1, *c2, *c3, *b2, *bp1, *pre0, *h0, *pre1;
    cudaGetSymbolAddress((void**)&Z,    g_Z);
    cudaGetSymbolAddress((void**)&H1,   g_H1);
    cudaGetSymbolAddress((void**)&H2,   g_H2);
    cudaGetSymbolAddress((void**)&H3,   g_H3);
    cudaGetSymbolAddress((void**)&W2,   g_W2);
    cudaGetSymbolAddress((void**)&c1,   g_c1);
    cudaGetSymbolAddress((void**)&c2,   g_c2);
    cudaGetSymbolAddress((void**)&c3,   g_c3);
    cudaGetSymbolAddress((void**)&b2,   g_b2);
    cudaGetSymbolAddress((void**)&bp1,  g_bp1);
    cudaGetSymbolAddress((void**)&pre0, g_pre0);
    cudaGetSymbolAddress((void**)&h0,   g_h0);
    cudaGetSymbolAddress((void**)&pre1, g_pre1);

    // 1) fuzzy membership -> Z [32768,200]
    fuzzy_kernel<<<(BS * IK + 255) / 256, 256>>>(x, fp, Z);

    // 2) compose W2 = w_ih0 @ fc3 @ fc2 @ fc1 @ fc0  (all NN)
    gemm_f32<64, 64, 16, 4, 4, false, 256><<<dim3(16, 2), 256>>>(fc3w, fc2w, nullptr, H1, NOUT, HFC, HFC);
    gemm_f32<64, 64, 16, 4, 4, false, 256><<<dim3(16, 2), 256>>>(H1,   fc1w, nullptr, H2, NOUT, HFC, HFC);
    gemm_f32<64, 64, 16, 4, 4, false, 256><<<dim3(4, 2),  256>>>(H2,   fc0w, nullptr, H3, NOUT, IK,  HFC);
    gemm_f32<64, 64, 16, 4, 4, false, 256><<<dim3(4, 8),  256>>>(wih0, H3,   nullptr, W2, HR,   IK,  NOUT);

    // 3) bias chain
    vecmat<<<8, 128>>>(fc1w, fc0b, fc1b, nullptr, c1, HFC, HFC);
    vecmat<<<8, 128>>>(fc2w, c1,   fc2b, nullptr, c2, HFC, HFC);
    vecmat<<<1, 128>>>(fc3w, c2,   fc3b, nullptr, c3, NOUT, HFC);
    vecmat<<<4, 128>>>(wih0, c3,   bih0, bhh0,    b2, HR,   NOUT);
    add2<<<1, 512>>>(bih1, bhh1, bp1, HR);

    // 4) pre0 = Z @ W2^T + b2   [32768,512], K=200
    gemm_f32<128, 128, 16, 8, 8, true, 256><<<dim3(HR / 128, BS / 128), 256>>>(Z, W2, b2, pre0, BS, HR, IK);

    // 5) RNN layer 0
    rnn_kernel<<<128, 256>>>(pre0, whh0, h0);

    // 6) pre1 = h0 @ w_ih1^T + (b_ih1+b_hh1)  [32768,512], K=512
    gemm_f32<128, 128, 16, 8, 8, true, 256><<<dim3(HR / 128, BS / 128), 256>>>(h0, wih1, bp1, pre1, BS, HR, HR);

    // 7) RNN layer 1 -> output
    rnn_kernel<<<128, 256>>>(pre1, whh1, out);
}